// round 10
// baseline (speedup 1.0000x reference)
#include <cuda_runtime.h>
#include <cuda_fp16.h>
#include <cstdint>

// ============================================================================
// Gps via mma.sync m16n8k16 fp16, single-term operands (validated 4.4e-4).
// R10 change: 4 warps/CTA, warp tile 64x64 (2m x 2n) -> per-chunk smem
// crossbar traffic 64KB -> 48KB (fragment duplication 4x/2x -> 2x/2x),
// flipping the binder from smem back to the tensor pipe.
//   agg0 = 0.5  * adj1 @ f1           [16384,256]
//   aggm = .125 * fold4(adj2) @ f2    (4-row sum fused in A fill)
//   h    = lrelu([feat[seed] | agg0] @ W1^T)   (gather+concat fused)
//   out  = lrelu([h | aggm] @ W2^T)
// CTA 128x128x32, grid(bn=2, bm=128) — bn-pairs L2-co-resident.
// ============================================================================

#define STAGE 20480              // A 10240 | B 10240
#define SMEM_TOTAL (2 * STAGE)   // 40960
#define OFF_B 10240
#define LDW 20                   // row stride in 4B words (80B)

__device__ float g_agg0[16384 * 256];
__device__ float g_aggm[16384 * 256];
__device__ float g_h[16384 * 256];
__device__ __half g_f1h[256 * 4096];
__device__ __half g_f2h[256 * 2048];
__device__ __half g_W1h[256 * 512];
__device__ __half g_W2h[256 * 512];

__device__ __forceinline__ uint32_t smem_u32(const void* p) {
    uint32_t a;
    asm("{ .reg .u64 t; cvta.to.shared.u64 t, %1; cvt.u32.u64 %0, t; }" : "=r"(a) : "l"(p));
    return a;
}
__device__ __forceinline__ void cpa16(uint32_t dst, const void* src) {
    asm volatile("cp.async.cg.shared.global [%0], [%1], 16;" :: "r"(dst), "l"(src));
}
__device__ __forceinline__ uint32_t pk(__half a, __half b) {
    __half2 t; t.x = a; t.y = b;
    return *(uint32_t*)&t;
}
__device__ __forceinline__ void mma_f16(float* c, const uint32_t* a, const uint32_t* b) {
    asm volatile(
        "mma.sync.aligned.m16n8k16.row.col.f32.f16.f16.f32 "
        "{%0,%1,%2,%3}, {%4,%5,%6,%7}, {%8,%9}, {%0,%1,%2,%3};"
        : "+f"(c[0]), "+f"(c[1]), "+f"(c[2]), "+f"(c[3])
        : "r"(a[0]), "r"(a[1]), "r"(a[2]), "r"(a[3]), "r"(b[0]), "r"(b[1]));
}

struct GDesc {
    const float* A1; int lda1; int KA1;   // cols [0,KA1): from A1 (gather/fold opt.)
    const int* seed; int fold;
    const float* A2; int lda2;            // cols [KA1,K): from A2
    const __half* B;                      // [256, K] n-major fp16
    float* C; int K; float scale; int lrelu;
};

__device__ __forceinline__ void gemm_body(const GDesc d, char* smem) {
    const uint32_t sb = smem_u32(smem);
    const int tid = threadIdx.x;                     // 128 threads
    const int l = tid & 31, wid = tid >> 5;          // 4 warps
    const int wm = wid & 1, wn = wid >> 1;           // 2m x 2n, warp 64x64
    const int bn = blockIdx.x, bm = blockIdx.y;      // bn fastest -> L2 A reuse
    const int NK = d.K >> 5;

    float acc[4][8][4];                              // mt x nt x frag
#pragma unroll
    for (int mt = 0; mt < 4; mt++)
#pragma unroll
        for (int nt = 0; nt < 8; nt++)
#pragma unroll
            for (int i = 0; i < 4; i++) acc[mt][nt][i] = 0.f;

    // hoisted source rows for this thread's 8 A granule-rows
    int srow[8];
#pragma unroll
    for (int j = 0; j < 8; j++) {
        const int m = bm * 128 + ((tid + j * 128) >> 3);
        srow[j] = d.seed ? d.seed[m] : (d.fold ? m * 4 : m);
    }

    auto ldgA = [&](int kc, float4* r) {
        const int k0 = kc << 5;
#pragma unroll
        for (int j = 0; j < 8; j++) {
            const int g = tid + j * 128;             // 1024 float4 granules
            const int row = g >> 3, kg = k0 + ((g & 7) << 2);
            if (kg < d.KA1) {
                const float* p = d.A1 + (size_t)srow[j] * d.lda1 + kg;
                if (d.fold) {
                    float4 v0 = *(const float4*)p;
                    float4 v1 = *(const float4*)(p + d.lda1);
                    float4 v2 = *(const float4*)(p + 2 * d.lda1);
                    float4 v3 = *(const float4*)(p + 3 * d.lda1);
                    r[j].x = (v0.x + v1.x) + (v2.x + v3.x);
                    r[j].y = (v0.y + v1.y) + (v2.y + v3.y);
                    r[j].z = (v0.z + v1.z) + (v2.z + v3.z);
                    r[j].w = (v0.w + v1.w) + (v2.w + v3.w);
                } else {
                    r[j] = *(const float4*)p;
                }
            } else {
                r[j] = *(const float4*)(d.A2 + (size_t)(bm * 128 + row) * d.lda2 +
                                        (kg - d.KA1));
            }
        }
    };
    auto stsA = [&](const float4* r, int s) {
        char* base = smem + s * STAGE;
#pragma unroll
        for (int j = 0; j < 8; j++) {
            const int g = tid + j * 128;
            const int row = g >> 3, q = g & 7;
            uint2 h;
            h.x = pk(__float2half(r[j].x), __float2half(r[j].y));
            h.y = pk(__float2half(r[j].z), __float2half(r[j].w));
            *(uint2*)(base + row * 80 + q * 8) = h;
        }
    };
    auto fillB = [&](int kc, int s) {
        const int k0 = kc << 5;
#pragma unroll
        for (int j = 0; j < 4; j++) {
            const int g = tid + j * 128;             // 512 granules of 16B
            const int row = g >> 2, q = g & 3;
            cpa16(sb + s * STAGE + OFF_B + row * 80 + q * 16,
                  d.B + (size_t)(bn * 128 + row) * d.K + k0 + q * 8);
        }
    };

    // prologue
    fillB(0, 0);
    asm volatile("cp.async.commit_group;" ::: "memory");
    {
        float4 a0[8];
        ldgA(0, a0);
        stsA(a0, 0);
    }

    for (int k = 0; k < NK; k++) {
        const int s = k & 1;
        __syncthreads();                             // stage s^1 free
        float4 ar2[8];
        if (k + 1 < NK) {
            fillB(k + 1, s ^ 1);
            asm volatile("cp.async.commit_group;" ::: "memory");
            ldgA(k + 1, ar2);                        // LDGs fly during compute(k)
            asm volatile("cp.async.wait_group 1;" ::: "memory");
        } else {
            asm volatile("cp.async.wait_group 0;" ::: "memory");
        }
        __syncthreads();                             // stage s visible

        const uint32_t* Ah = (const uint32_t*)(smem + s * STAGE);
        const uint32_t* Bh = (const uint32_t*)(smem + s * STAGE + OFF_B);
#pragma unroll
        for (int ks = 0; ks < 2; ks++) {
            const int kw = ks * 8 + (l & 3);
            uint32_t a[4][4];
#pragma unroll
            for (int mt = 0; mt < 4; mt++) {
                const int r = wm * 64 + mt * 16 + (l >> 2);
                a[mt][0] = Ah[r * LDW + kw];
                a[mt][1] = Ah[(r + 8) * LDW + kw];
                a[mt][2] = Ah[r * LDW + kw + 4];
                a[mt][3] = Ah[(r + 8) * LDW + kw + 4];
            }
#pragma unroll
            for (int nt = 0; nt < 8; nt++) {
                const int n = wn * 64 + nt * 8 + (l >> 2);
                uint32_t b[2];
                b[0] = Bh[n * LDW + kw];
                b[1] = Bh[n * LDW + kw + 4];
#pragma unroll
                for (int mt = 0; mt < 4; mt++) mma_f16(acc[mt][nt], a[mt], b);
            }
        }
        if (k + 1 < NK) stsA(ar2, s ^ 1);            // hidden under MMA tail
    }

    // epilogue (all outputs ldc = 256)
#pragma unroll
    for (int mt = 0; mt < 4; mt++) {
        const int r0 = bm * 128 + wm * 64 + mt * 16 + (l >> 2);
#pragma unroll
        for (int nt = 0; nt < 8; nt++) {
            const int c0 = bn * 128 + wn * 64 + nt * 8 + 2 * (l & 3);
#pragma unroll
            for (int h = 0; h < 2; h++) {
                float2 v;
                v.x = acc[mt][nt][2 * h + 0] * d.scale;
                v.y = acc[mt][nt][2 * h + 1] * d.scale;
                if (d.lrelu) {
                    v.x = (v.x >= 0.f) ? v.x : 0.01f * v.x;
                    v.y = (v.y >= 0.f) ? v.y : 0.01f * v.y;
                }
                *(float2*)(d.C + (size_t)(r0 + h * 8) * 256 + c0) = v;
            }
        }
    }
}

__global__ void __launch_bounds__(128, 2)
gemm_mma(GDesc d) {
    extern __shared__ char smem[];
    gemm_body(d, smem);
}

// [K,256] fp32 -> [256,K] fp16 (transpose + RN convert)
__global__ void tconv_h(const float* __restrict__ in, __half* __restrict__ o, int K) {
    __shared__ float t[32][33];
    const int k0 = blockIdx.x * 32, n0 = blockIdx.y * 32;
    const int tx = threadIdx.x, ty = threadIdx.y;
#pragma unroll
    for (int i = 0; i < 32; i += 8)
        t[ty + i][tx] = in[(size_t)(k0 + ty + i) * 256 + n0 + tx];
    __syncthreads();
#pragma unroll
    for (int i = 0; i < 32; i += 8)
        o[(size_t)(n0 + ty + i) * K + k0 + tx] = __float2half(t[tx][ty + i]);
}
// [256,K] fp32 -> fp16 elementwise (W already n-major)
__global__ void wconv_h(const float* __restrict__ in, __half* __restrict__ o) {
    const int i = blockIdx.x * 256 + threadIdx.x;
    o[i] = __float2half(in[i]);
}

extern "C" void kernel_launch(void* const* d_in, const int* in_sizes, int n_in,
                              void* d_out, int out_size) {
    const float* feat = (const float*)d_in[0];   // [100000,256]
    const float* adj1 = (const float*)d_in[1];   // [16384,4096]
    const float* f1 = (const float*)d_in[2];     // [4096,256]
    const float* adj2 = (const float*)d_in[3];   // [65536,2048]
    const float* f2 = (const float*)d_in[4];     // [2048,256]
    const float* W1 = (const float*)d_in[5];     // [256,512]
    const float* W2 = (const float*)d_in[6];     // [256,512]
    const int* seed = (const int*)d_in[7];       // [16384]
    float* out = (float*)d_out;                  // [16384,256]

    float *agg0, *aggm, *h;
    __half *f1h, *f2h, *W1h, *W2h;
    cudaGetSymbolAddress((void**)&agg0, g_agg0);
    cudaGetSymbolAddress((void**)&aggm, g_aggm);
    cudaGetSymbolAddress((void**)&h, g_h);
    cudaGetSymbolAddress((void**)&f1h, g_f1h);
    cudaGetSymbolAddress((void**)&f2h, g_f2h);
    cudaGetSymbolAddress((void**)&W1h, g_W1h);
    cudaGetSymbolAddress((void**)&W2h, g_W2h);

    cudaFuncSetAttribute(gemm_mma, cudaFuncAttributeMaxDynamicSharedMemorySize, SMEM_TOTAL);

    tconv_h<<<dim3(128, 8), dim3(32, 8)>>>(f1, f1h, 4096);
    tconv_h<<<dim3(64, 8), dim3(32, 8)>>>(f2, f2h, 2048);
    wconv_h<<<512, 256>>>(W1, W1h);
    wconv_h<<<512, 256>>>(W2, W2h);

    GDesc dG1 = {adj1, 4096, 4096, nullptr, 0, nullptr, 0, f1h, agg0, 4096, 0.5f, 0};
    GDesc dG2 = {adj2, 2048, 2048, nullptr, 1, nullptr, 0, f2h, aggm, 2048, 0.125f, 0};
    GDesc dG3 = {feat, 256, 256, seed, 0, agg0, 256, W1h, h, 512, 1.0f, 1};
    GDesc dG4 = {h, 256, 256, nullptr, 0, aggm, 256, W2h, out, 512, 1.0f, 1};

    dim3 grid(2, 128), blk(128);
    gemm_mma<<<grid, blk, SMEM_TOTAL>>>(dG1);   // agg0
    gemm_mma<<<grid, blk, SMEM_TOTAL>>>(dG2);   // aggm (fold4 fused)
    gemm_mma<<<grid, blk, SMEM_TOTAL>>>(dG3);   // h  (gather+concat fused)
    gemm_mma<<<grid, blk, SMEM_TOTAL>>>(dG4);   // out
}

// round 11
// speedup vs baseline: 1.4599x; 1.4599x over previous
#include <cuda_runtime.h>
#include <cuda_fp16.h>
#include <cstdint>

// ============================================================================
// Gps via mma.sync m16n8k16 fp16, single-term operands (validated 4.4e-4).
// R11: back to R9's proven 256-thr 2m x 4n shape; K-chunk 64, ONE barrier per
// chunk, A reg-buffer in two 4-float4 batches interleaved with compute halves.
//   agg0 = 0.5  * adj1 @ f1           [16384,256]
//   aggm = .125 * fold4(adj2) @ f2    (4-row sum fused in A fill)
//   h    = lrelu([feat[seed] | agg0] @ W1^T)   (gather+concat fused)
//   out  = lrelu([h | aggm] @ W2^T)
// CTA 128x128x64, grid(bn=2, bm=128) — bn-pairs L2-co-resident.
// ============================================================================

#define ASTG 18432               // 128 rows x 144B (64 half + pad)
#define OFFB 36864               // B stages at 36864 + s*18432
#define SMEM_TOTAL 73728
#define LDW 36                   // row stride in 4B words

__device__ float g_agg0[16384 * 256];
__device__ float g_aggm[16384 * 256];
__device__ float g_h[16384 * 256];
__device__ __half g_f1h[256 * 4096];
__device__ __half g_f2h[256 * 2048];
__device__ __half g_Wh[2][256 * 512];

__device__ __forceinline__ uint32_t smem_u32(const void* p) {
    uint32_t a;
    asm("{ .reg .u64 t; cvta.to.shared.u64 t, %1; cvt.u32.u64 %0, t; }" : "=r"(a) : "l"(p));
    return a;
}
__device__ __forceinline__ void cpa16(uint32_t dst, const void* src) {
    asm volatile("cp.async.cg.shared.global [%0], [%1], 16;" :: "r"(dst), "l"(src));
}
__device__ __forceinline__ uint32_t pk(__half a, __half b) {
    __half2 t; t.x = a; t.y = b;
    return *(uint32_t*)&t;
}
__device__ __forceinline__ void mma_f16(float* c, const uint32_t* a, const uint32_t* b) {
    asm volatile(
        "mma.sync.aligned.m16n8k16.row.col.f32.f16.f16.f32 "
        "{%0,%1,%2,%3}, {%4,%5,%6,%7}, {%8,%9}, {%0,%1,%2,%3};"
        : "+f"(c[0]), "+f"(c[1]), "+f"(c[2]), "+f"(c[3])
        : "r"(a[0]), "r"(a[1]), "r"(a[2]), "r"(a[3]), "r"(b[0]), "r"(b[1]));
}

struct GDesc {
    const float* A1; int lda1; int KA1;   // cols [0,KA1): from A1 (gather/fold opt.)
    const int* seed; int fold;
    const float* A2; int lda2;            // cols [KA1,K): from A2
    const __half* B;                      // [256, K] n-major fp16
    float* C; int K; float scale; int lrelu;
};

__device__ __forceinline__ void gemm_body(const GDesc d, char* smem) {
    const uint32_t sb = smem_u32(smem);
    const int tid = threadIdx.x;                     // 256 threads
    const int l = tid & 31, wid = tid >> 5;
    const int wm = wid & 1, wn = wid >> 1;           // 2m x 4n, warp 64x32
    const int bn = blockIdx.x, bm = blockIdx.y;      // bn fastest -> L2 A reuse
    const int NK = d.K >> 6;

    float acc[4][4][4];
#pragma unroll
    for (int mt = 0; mt < 4; mt++)
#pragma unroll
        for (int nt = 0; nt < 4; nt++)
#pragma unroll
            for (int i = 0; i < 4; i++) acc[mt][nt][i] = 0.f;

    // thread's 8 A granule-rows: row_j = (tid>>4) + 16*j  (granule g = tid + j*256)
    const int rbase = tid >> 4;

    // one batch = 4 granules (j = hb*4 .. hb*4+3)
    auto ldgA = [&](int kc, int hb, float4* r) {
        const int k0 = kc << 6;
#pragma unroll
        for (int j = 0; j < 4; j++) {
            const int row = rbase + 16 * (hb * 4 + j);
            const int kg = k0 + ((tid & 15) << 2);
            if (kg < d.KA1) {
                const int sr = d.seed ? d.seed[bm * 128 + row]
                                      : (d.fold ? (bm * 128 + row) * 4 : bm * 128 + row);
                const float* p = d.A1 + (size_t)sr * d.lda1 + kg;
                if (d.fold) {
                    float4 v0 = *(const float4*)p;
                    float4 v1 = *(const float4*)(p + d.lda1);
                    float4 v2 = *(const float4*)(p + 2 * d.lda1);
                    float4 v3 = *(const float4*)(p + 3 * d.lda1);
                    r[j].x = (v0.x + v1.x) + (v2.x + v3.x);
                    r[j].y = (v0.y + v1.y) + (v2.y + v3.y);
                    r[j].z = (v0.z + v1.z) + (v2.z + v3.z);
                    r[j].w = (v0.w + v1.w) + (v2.w + v3.w);
                } else {
                    r[j] = *(const float4*)p;
                }
            } else {
                r[j] = *(const float4*)(d.A2 + (size_t)(bm * 128 + row) * d.lda2 +
                                        (kg - d.KA1));
            }
        }
    };
    auto stsA = [&](const float4* r, int hb, int s) {
        char* base = smem + s * ASTG;
        const int q = tid & 15;
#pragma unroll
        for (int j = 0; j < 4; j++) {
            const int row = rbase + 16 * (hb * 4 + j);
            uint2 h;
            h.x = pk(__float2half(r[j].x), __float2half(r[j].y));
            h.y = pk(__float2half(r[j].z), __float2half(r[j].w));
            *(uint2*)(base + row * 144 + q * 8) = h;
        }
    };
    auto fillB = [&](int kc, int s) {
        const int k0 = kc << 6;
#pragma unroll
        for (int j = 0; j < 4; j++) {
            const int g = tid + j * 256;             // 1024 granules of 16B
            const int row = g >> 3, q = g & 7;
            cpa16(sb + OFFB + s * ASTG + row * 144 + q * 16,
                  d.B + (size_t)(bn * 128 + row) * d.K + k0 + q * 8);
        }
        asm volatile("cp.async.commit_group;" ::: "memory");
    };

    // prologue: stage 0
    fillB(0, 0);
    {
        float4 a0[4];
        ldgA(0, 0, a0); stsA(a0, 0, 0);
        ldgA(0, 1, a0); stsA(a0, 1, 0);
    }

    for (int k = 0; k < NK; k++) {
        const int s = k & 1;
        asm volatile("cp.async.wait_group 0;" ::: "memory");   // B(k) arrived
        __syncthreads();   // A(k)+B(k) visible; stage s^1 free for overwrite

        if (k + 1 < NK) fillB(k + 1, s ^ 1);
        float4 ar[4];
        if (k + 1 < NK) ldgA(k + 1, 0, ar);

        const uint32_t* Ah = (const uint32_t*)(smem + s * ASTG);
        const uint32_t* Bh = (const uint32_t*)(smem + OFFB + s * ASTG);

#pragma unroll
        for (int half = 0; half < 2; half++) {
#pragma unroll
            for (int ki = 0; ki < 2; ki++) {
                const int ks = half * 2 + ki;
                const int kw = ks * 8 + (l & 3);
                uint32_t a[4][4];
#pragma unroll
                for (int mt = 0; mt < 4; mt++) {
                    const int r = wm * 64 + mt * 16 + (l >> 2);
                    a[mt][0] = Ah[r * LDW + kw];
                    a[mt][1] = Ah[(r + 8) * LDW + kw];
                    a[mt][2] = Ah[r * LDW + kw + 4];
                    a[mt][3] = Ah[(r + 8) * LDW + kw + 4];
                }
#pragma unroll
                for (int nt = 0; nt < 4; nt++) {
                    const int n = wn * 32 + nt * 8 + (l >> 2);
                    uint32_t b[2];
                    b[0] = Bh[n * LDW + kw];
                    b[1] = Bh[n * LDW + kw + 4];
#pragma unroll
                    for (int mt = 0; mt < 4; mt++) mma_f16(acc[mt][nt], a[mt], b);
                }
            }
            if (k + 1 < NK) {
                stsA(ar, half, s ^ 1);               // batch done: park it
                if (half == 0) ldgA(k + 1, 1, ar);   // fetch second batch
            }
        }
    }

    // epilogue (all outputs ldc = 256)
#pragma unroll
    for (int mt = 0; mt < 4; mt++) {
        const int r0 = bm * 128 + wm * 64 + mt * 16 + (l >> 2);
#pragma unroll
        for (int nt = 0; nt < 4; nt++) {
            const int c0 = bn * 128 + wn * 32 + nt * 8 + 2 * (l & 3);
#pragma unroll
            for (int h = 0; h < 2; h++) {
                float2 v;
                v.x = acc[mt][nt][2 * h + 0] * d.scale;
                v.y = acc[mt][nt][2 * h + 1] * d.scale;
                if (d.lrelu) {
                    v.x = (v.x >= 0.f) ? v.x : 0.01f * v.x;
                    v.y = (v.y >= 0.f) ? v.y : 0.01f * v.y;
                }
                *(float2*)(d.C + (size_t)(r0 + h * 8) * 256 + c0) = v;
            }
        }
    }
}

__global__ void __launch_bounds__(256, 2)
gemm_mma(GDesc d) {
    extern __shared__ char smem[];
    gemm_body(d, smem);
}

// [K,256] fp32 -> [256,K] fp16 (transpose + RN convert)
__global__ void tconv_h(const float* __restrict__ in, __half* __restrict__ o, int K) {
    __shared__ float t[32][33];
    const int k0 = blockIdx.x * 32, n0 = blockIdx.y * 32;
    const int tx = threadIdx.x, ty = threadIdx.y;
#pragma unroll
    for (int i = 0; i < 32; i += 8)
        t[ty + i][tx] = in[(size_t)(k0 + ty + i) * 256 + n0 + tx];
    __syncthreads();
#pragma unroll
    for (int i = 0; i < 32; i += 8)
        o[(size_t)(n0 + ty + i) * K + k0 + tx] = __float2half(t[tx][ty + i]);
}
// W1 and W2 -> fp16 in one launch (keeps big GEMM at launch #4 for ncu)
__global__ void wconv2_h(const float* __restrict__ w1, const float* __restrict__ w2,
                         __half* __restrict__ o1, __half* __restrict__ o2) {
    const int i = blockIdx.x * 256 + threadIdx.x;
    if (i < 256 * 512) o1[i] = __float2half(w1[i]);
    else o2[i - 256 * 512] = __float2half(w2[i - 256 * 512]);
}

extern "C" void kernel_launch(void* const* d_in, const int* in_sizes, int n_in,
                              void* d_out, int out_size) {
    const float* feat = (const float*)d_in[0];   // [100000,256]
    const float* adj1 = (const float*)d_in[1];   // [16384,4096]
    const float* f1 = (const float*)d_in[2];     // [4096,256]
    const float* adj2 = (const float*)d_in[3];   // [65536,2048]
    const float* f2 = (const float*)d_in[4];     // [2048,256]
    const float* W1 = (const float*)d_in[5];     // [256,512]
    const float* W2 = (const float*)d_in[6];     // [256,512]
    const int* seed = (const int*)d_in[7];       // [16384]
    float* out = (float*)d_out;                  // [16384,256]

    float *agg0, *aggm, *h;
    __half *f1h, *f2h, *Wh;
    cudaGetSymbolAddress((void**)&agg0, g_agg0);
    cudaGetSymbolAddress((void**)&aggm, g_aggm);
    cudaGetSymbolAddress((void**)&h, g_h);
    cudaGetSymbolAddress((void**)&f1h, g_f1h);
    cudaGetSymbolAddress((void**)&f2h, g_f2h);
    cudaGetSymbolAddress((void**)&Wh, g_Wh);

    cudaFuncSetAttribute(gemm_mma, cudaFuncAttributeMaxDynamicSharedMemorySize, SMEM_TOTAL);

    tconv_h<<<dim3(128, 8), dim3(32, 8)>>>(f1, f1h, 4096);
    tconv_h<<<dim3(64, 8), dim3(32, 8)>>>(f2, f2h, 2048);
    wconv2_h<<<1024, 256>>>(W1, W2, Wh, Wh + 256 * 512);

    GDesc dG1 = {adj1, 4096, 4096, nullptr, 0, nullptr, 0, f1h, agg0, 4096, 0.5f, 0};
    GDesc dG2 = {adj2, 2048, 2048, nullptr, 1, nullptr, 0, f2h, aggm, 2048, 0.125f, 0};
    GDesc dG3 = {feat, 256, 256, seed, 0, agg0, 256, Wh, h, 512, 1.0f, 1};
    GDesc dG4 = {h, 256, 256, nullptr, 0, aggm, 256, Wh + 256 * 512, out, 512, 1.0f, 1};

    dim3 grid(2, 128), blk(256);
    gemm_mma<<<grid, blk, SMEM_TOTAL>>>(dG1);   // launch #4 -> ncu capture target
    gemm_mma<<<grid, blk, SMEM_TOTAL>>>(dG2);   // aggm (fold4 fused)
    gemm_mma<<<grid, blk, SMEM_TOTAL>>>(dG3);   // h  (gather+concat fused)
    gemm_mma<<<grid, blk, SMEM_TOTAL>>>(dG4);   // out
}

// round 12
// speedup vs baseline: 1.7798x; 1.2191x over previous
#include <cuda_runtime.h>
#include <cuda_fp16.h>
#include <cstdint>

// ============================================================================
// Gps, fp16 single-term mma.sync m16n8k16 (validated rel_err 4.40e-4).
// R12: adj2 fold4+cvt moved to a streaming prepass (bit-identical math);
// agg0/aggm/h stored as fp16 directly into concat buffers -> G2/G3/G4 are
// pure-fp16 GEMMs (A and B both cp.async, 3-stage pipeline, no in-loop LDG).
// G1 keeps the fused fp32-A path (pre-converting adj1 is ~neutral).
//   Acat1 = [fp16(feat[seed]) | fp16(0.5*adj1@f1)]      [16384,512] half
//   A2h   = fp16(fold4(adj2))                           [16384,2048] half
//   Acat2 = [fp16(lrelu(Acat1@W1^T)) | fp16(0.125*A2h@f2)]
//   out   = lrelu(Acat2 @ W2^T)  fp32
// CTA 128x128x64, 8 warps (2m x 4n), grid(bn=2, bm=128).
// ============================================================================

#define ASTG 18432               // F variant: A stage 128 x 144B
#define OFFB 36864               // F variant: B stages at 36864 + s*18432
#define SMEM_F 73728
#define PSTG 36864               // P variant stage: A 18432 + B 18432
#define SMEM_P (3 * 36864)       // 110592 (3 stages)
#define LDW 36                   // row stride in 4B words

__device__ __half g_A2h[16384 * 2048];
__device__ __half g_Acat1[16384 * 512];
__device__ __half g_Acat2[16384 * 512];
__device__ __half g_f1h[256 * 4096];
__device__ __half g_f2h[256 * 2048];
__device__ __half g_Wh[2][256 * 512];

__device__ __forceinline__ uint32_t smem_u32(const void* p) {
    uint32_t a;
    asm("{ .reg .u64 t; cvta.to.shared.u64 t, %1; cvt.u32.u64 %0, t; }" : "=r"(a) : "l"(p));
    return a;
}
__device__ __forceinline__ void cpa16(uint32_t dst, const void* src) {
    asm volatile("cp.async.cg.shared.global [%0], [%1], 16;" :: "r"(dst), "l"(src));
}
__device__ __forceinline__ uint32_t pk(__half a, __half b) {
    __half2 t; t.x = a; t.y = b;
    return *(uint32_t*)&t;
}
__device__ __forceinline__ void mma_f16(float* c, const uint32_t* a, const uint32_t* b) {
    asm volatile(
        "mma.sync.aligned.m16n8k16.row.col.f32.f16.f16.f32 "
        "{%0,%1,%2,%3}, {%4,%5,%6,%7}, {%8,%9}, {%0,%1,%2,%3};"
        : "+f"(c[0]), "+f"(c[1]), "+f"(c[2]), "+f"(c[3])
        : "r"(a[0]), "r"(a[1]), "r"(a[2]), "r"(a[3]), "r"(b[0]), "r"(b[1]));
}

// ============================================================================
// F variant (G1 only): A fp32 [16384,4096] fused LDG+cvt path, K-chunk 64,
// 2 stages, epilogue -> fp16 into Acat1 cols [256:512).
// ============================================================================
__global__ void __launch_bounds__(256, 2)
gemm_f(const float* __restrict__ A, const __half* __restrict__ B,
       __half* __restrict__ C) {
    extern __shared__ char smem[];
    const uint32_t sb = smem_u32(smem);
    const int tid = threadIdx.x;
    const int l = tid & 31, wid = tid >> 5;
    const int wm = wid & 1, wn = wid >> 1;
    const int bn = blockIdx.x, bm = blockIdx.y;
    const int NK = 64;                               // K = 4096

    float acc[4][4][4];
#pragma unroll
    for (int mt = 0; mt < 4; mt++)
#pragma unroll
        for (int nt = 0; nt < 4; nt++)
#pragma unroll
            for (int i = 0; i < 4; i++) acc[mt][nt][i] = 0.f;

    const int rbase = tid >> 4;
    const int kq = (tid & 15) << 2;

    auto ldgA = [&](int kc, int hb, float4* r) {
#pragma unroll
        for (int j = 0; j < 4; j++) {
            const int row = rbase + 16 * (hb * 4 + j);
            r[j] = *(const float4*)(A + (size_t)(bm * 128 + row) * 4096 +
                                    (kc << 6) + kq);
        }
    };
    auto stsA = [&](const float4* r, int hb, int s) {
        char* base = smem + s * ASTG;
        const int q = tid & 15;
#pragma unroll
        for (int j = 0; j < 4; j++) {
            const int row = rbase + 16 * (hb * 4 + j);
            uint2 h;
            h.x = pk(__float2half(r[j].x), __float2half(r[j].y));
            h.y = pk(__float2half(r[j].z), __float2half(r[j].w));
            *(uint2*)(base + row * 144 + q * 8) = h;
        }
    };
    auto fillB = [&](int kc, int s) {
#pragma unroll
        for (int j = 0; j < 4; j++) {
            const int g = tid + j * 256;
            const int row = g >> 3, q = g & 7;
            cpa16(sb + OFFB + s * ASTG + row * 144 + q * 16,
                  B + (size_t)(bn * 128 + row) * 4096 + (kc << 6) + q * 8);
        }
        asm volatile("cp.async.commit_group;" ::: "memory");
    };

    fillB(0, 0);
    {
        float4 a0[4];
        ldgA(0, 0, a0); stsA(a0, 0, 0);
        ldgA(0, 1, a0); stsA(a0, 1, 0);
    }

    for (int k = 0; k < NK; k++) {
        const int s = k & 1;
        asm volatile("cp.async.wait_group 0;" ::: "memory");
        __syncthreads();

        if (k + 1 < NK) fillB(k + 1, s ^ 1);
        float4 ar[4];
        if (k + 1 < NK) ldgA(k + 1, 0, ar);

        const uint32_t* Ah = (const uint32_t*)(smem + s * ASTG);
        const uint32_t* Bh = (const uint32_t*)(smem + OFFB + s * ASTG);
#pragma unroll
        for (int half = 0; half < 2; half++) {
#pragma unroll
            for (int ki = 0; ki < 2; ki++) {
                const int ks = half * 2 + ki;
                const int kw = ks * 8 + (l & 3);
                uint32_t a[4][4];
#pragma unroll
                for (int mt = 0; mt < 4; mt++) {
                    const int r = wm * 64 + mt * 16 + (l >> 2);
                    a[mt][0] = Ah[r * LDW + kw];
                    a[mt][1] = Ah[(r + 8) * LDW + kw];
                    a[mt][2] = Ah[r * LDW + kw + 4];
                    a[mt][3] = Ah[(r + 8) * LDW + kw + 4];
                }
#pragma unroll
                for (int nt = 0; nt < 4; nt++) {
                    const int n = wn * 32 + nt * 8 + (l >> 2);
                    uint32_t b[2];
                    b[0] = Bh[n * LDW + kw];
                    b[1] = Bh[n * LDW + kw + 4];
#pragma unroll
                    for (int mt = 0; mt < 4; mt++) mma_f16(acc[mt][nt], a[mt], b);
                }
            }
            if (k + 1 < NK) {
                stsA(ar, half, s ^ 1);
                if (half == 0) ldgA(k + 1, 1, ar);
            }
        }
    }

    // epilogue: scale 0.5, fp16 into Acat1[:, 256:512) (ldc 512 halfs)
#pragma unroll
    for (int mt = 0; mt < 4; mt++) {
        const int r0 = bm * 128 + wm * 64 + mt * 16 + (l >> 2);
#pragma unroll
        for (int nt = 0; nt < 4; nt++) {
            const int c0 = bn * 128 + wn * 32 + nt * 8 + 2 * (l & 3);
#pragma unroll
            for (int h = 0; h < 2; h++) {
                const float vx = acc[mt][nt][2 * h + 0] * 0.5f;
                const float vy = acc[mt][nt][2 * h + 1] * 0.5f;
                *(uint32_t*)(C + (size_t)(r0 + h * 8) * 512 + c0) =
                    pk(__float2half(vx), __float2half(vy));
            }
        }
    }
}

// ============================================================================
// P variant (G2/G3/G4): both operands fp16 via cp.async, 3 stages, K-chunk 64.
//   A [16384, K] half row-major; B [256, K] half n-major.
//   EPIH=1: C half (ldc halfs); EPIH=0: C float (ldc floats).
// ============================================================================
template <int EPIH>
__global__ void __launch_bounds__(256, 2)
gemm_p(const __half* __restrict__ A, const __half* __restrict__ B,
       void* __restrict__ Cv, int K, float scale, int lrelu, int ldc) {
    extern __shared__ char smem[];
    const uint32_t sb = smem_u32(smem);
    const int tid = threadIdx.x;
    const int l = tid & 31, wid = tid >> 5;
    const int wm = wid & 1, wn = wid >> 1;
    const int bn = blockIdx.x, bm = blockIdx.y;
    const int NK = K >> 6;

    float acc[4][4][4];
#pragma unroll
    for (int mt = 0; mt < 4; mt++)
#pragma unroll
        for (int nt = 0; nt < 4; nt++)
#pragma unroll
            for (int i = 0; i < 4; i++) acc[mt][nt][i] = 0.f;

    auto fill = [&](int kc, int st) {
        const uint32_t base = sb + st * PSTG;
        const int k0 = kc << 6;
#pragma unroll
        for (int j = 0; j < 4; j++) {
            const int g = tid + j * 256;
            const int row = g >> 3, q = g & 7;
            cpa16(base + row * 144 + q * 16,
                  A + (size_t)(bm * 128 + row) * K + k0 + q * 8);
            cpa16(base + 18432 + row * 144 + q * 16,
                  B + (size_t)(bn * 128 + row) * K + k0 + q * 8);
        }
    };

    fill(0, 0);
    asm volatile("cp.async.commit_group;" ::: "memory");
    fill(1, 1);
    asm volatile("cp.async.commit_group;" ::: "memory");

    int st = 0, stF = 2;
    for (int k = 0; k < NK; k++) {
        asm volatile("cp.async.wait_group 1;" ::: "memory");   // chunk k resident
        __syncthreads();                                       // visible; old stage free

        if (k + 2 < NK) fill(k + 2, stF);
        asm volatile("cp.async.commit_group;" ::: "memory");   // unconditional

        const uint32_t* Ah = (const uint32_t*)(smem + st * PSTG);
        const uint32_t* Bh = (const uint32_t*)(smem + st * PSTG + 18432);
#pragma unroll
        for (int ks = 0; ks < 4; ks++) {
            const int kw = ks * 8 + (l & 3);
            uint32_t a[4][4];
#pragma unroll
            for (int mt = 0; mt < 4; mt++) {
                const int r = wm * 64 + mt * 16 + (l >> 2);
                a[mt][0] = Ah[r * LDW + kw];
                a[mt][1] = Ah[(r + 8) * LDW + kw];
                a[mt][2] = Ah[r * LDW + kw + 4];
                a[mt][3] = Ah[(r + 8) * LDW + kw + 4];
            }
#pragma unroll
            for (int nt = 0; nt < 4; nt++) {
                const int n = wn * 32 + nt * 8 + (l >> 2);
                uint32_t b[2];
                b[0] = Bh[n * LDW + kw];
                b[1] = Bh[n * LDW + kw + 4];
#pragma unroll
                for (int mt = 0; mt < 4; mt++) mma_f16(acc[mt][nt], a[mt], b);
            }
        }
        st++; if (st == 3) st = 0;
        stF++; if (stF == 3) stF = 0;
    }

#pragma unroll
    for (int mt = 0; mt < 4; mt++) {
        const int r0 = bm * 128 + wm * 64 + mt * 16 + (l >> 2);
#pragma unroll
        for (int nt = 0; nt < 4; nt++) {
            const int c0 = bn * 128 + wn * 32 + nt * 8 + 2 * (l & 3);
#pragma unroll
            for (int h = 0; h < 2; h++) {
                float vx = acc[mt][nt][2 * h + 0] * scale;
                float vy = acc[mt][nt][2 * h + 1] * scale;
                if (lrelu) {
                    vx = (vx >= 0.f) ? vx : 0.01f * vx;
                    vy = (vy >= 0.f) ? vy : 0.01f * vy;
                }
                if (EPIH) {
                    *(uint32_t*)((__half*)Cv + (size_t)(r0 + h * 8) * ldc + c0) =
                        pk(__float2half(vx), __float2half(vy));
                } else {
                    float2 v; v.x = vx; v.y = vy;
                    *(float2*)((float*)Cv + (size_t)(r0 + h * 8) * ldc + c0) = v;
                }
            }
        }
    }
}

// ---- prepasses ----

// A2h[m][k] = fp16( sum_{i<4} adj2[4m+i][k] )   (streaming fold + cvt)
__global__ void fold4cvt(const float* __restrict__ in, __half* __restrict__ out) {
    const int g = blockIdx.x * 256 + threadIdx.x;    // 16384*512 granules
    const int m = g >> 9, k4 = (g & 511) << 2;
    const float* p = in + (size_t)m * 4 * 2048 + k4;
    float4 v0 = *(const float4*)p;
    float4 v1 = *(const float4*)(p + 2048);
    float4 v2 = *(const float4*)(p + 4096);
    float4 v3 = *(const float4*)(p + 6144);
    uint2 h;
    h.x = pk(__float2half((v0.x + v1.x) + (v2.x + v3.x)),
             __float2half((v0.y + v1.y) + (v2.y + v3.y)));
    h.y = pk(__float2half((v0.z + v1.z) + (v2.z + v3.z)),
             __float2half((v0.w + v1.w) + (v2.w + v3.w)));
    *(uint2*)(out + (size_t)m * 2048 + k4) = h;
}

// Acat1[m][0:256) = fp16(feat[seed[m]])
__global__ void gather_cvt(const float4* __restrict__ feat, const int* __restrict__ seed,
                           __half* __restrict__ acat) {
    const int g = blockIdx.x * 256 + threadIdx.x;    // 16384*64
    const int m = g >> 6, q = g & 63;
    float4 v = feat[(size_t)seed[m] * 64 + q];
    uint2 h;
    h.x = pk(__float2half(v.x), __float2half(v.y));
    h.y = pk(__float2half(v.z), __float2half(v.w));
    *(uint2*)(acat + (size_t)m * 512 + q * 4) = h;
}

// [K,256] fp32 -> [256,K] fp16 (transpose + RN)
__global__ void tconv_h(const float* __restrict__ in, __half* __restrict__ o, int K) {
    __shared__ float t[32][33];
    const int k0 = blockIdx.x * 32, n0 = blockIdx.y * 32;
    const int tx = threadIdx.x, ty = threadIdx.y;
#pragma unroll
    for (int i = 0; i < 32; i += 8)
        t[ty + i][tx] = in[(size_t)(k0 + ty + i) * 256 + n0 + tx];
    __syncthreads();
#pragma unroll
    for (int i = 0; i < 32; i += 8)
        o[(size_t)(n0 + ty + i) * K + k0 + tx] = __float2half(t[tx][ty + i]);
}
__global__ void wconv2_h(const float* __restrict__ w1, const float* __restrict__ w2,
                         __half* __restrict__ o1, __half* __restrict__ o2) {
    const int i = blockIdx.x * 256 + threadIdx.x;
    if (i < 256 * 512) o1[i] = __float2half(w1[i]);
    else o2[i - 256 * 512] = __float2half(w2[i - 256 * 512]);
}

extern "C" void kernel_launch(void* const* d_in, const int* in_sizes, int n_in,
                              void* d_out, int out_size) {
    const float* feat = (const float*)d_in[0];
    const float* adj1 = (const float*)d_in[1];
    const float* f1 = (const float*)d_in[2];
    const float* adj2 = (const float*)d_in[3];
    const float* f2 = (const float*)d_in[4];
    const float* W1 = (const float*)d_in[5];
    const float* W2 = (const float*)d_in[6];
    const int* seed = (const int*)d_in[7];
    float* out = (float*)d_out;

    __half *A2h, *Acat1, *Acat2, *f1h, *f2h, *Wh;
    cudaGetSymbolAddress((void**)&A2h, g_A2h);
    cudaGetSymbolAddress((void**)&Acat1, g_Acat1);
    cudaGetSymbolAddress((void**)&Acat2, g_Acat2);
    cudaGetSymbolAddress((void**)&f1h, g_f1h);
    cudaGetSymbolAddress((void**)&f2h, g_f2h);
    cudaGetSymbolAddress((void**)&Wh, g_Wh);

    cudaFuncSetAttribute(gemm_f, cudaFuncAttributeMaxDynamicSharedMemorySize, SMEM_F);
    cudaFuncSetAttribute(gemm_p<0>, cudaFuncAttributeMaxDynamicSharedMemorySize, SMEM_P);
    cudaFuncSetAttribute(gemm_p<1>, cudaFuncAttributeMaxDynamicSharedMemorySize, SMEM_P);

    tconv_h<<<dim3(128, 8), dim3(32, 8)>>>(f1, f1h, 4096);
    tconv_h<<<dim3(64, 8), dim3(32, 8)>>>(f2, f2h, 2048);
    wconv2_h<<<1024, 256>>>(W1, W2, Wh, Wh + 256 * 512);
    gather_cvt<<<4096, 256>>>((const float4*)feat, seed, Acat1);
    fold4cvt<<<32768, 256>>>(adj2, A2h);

    dim3 grid(2, 128), blk(256);
    // G1 (launch #6 -> ncu target): Acat1[:,256:512) = fp16(0.5 * adj1 @ f1)
    gemm_f<<<grid, blk, SMEM_F>>>(adj1, f1h, Acat1 + 256);
    // G2: Acat2[:,256:512) = fp16(0.125 * A2h @ f2)
    gemm_p<1><<<grid, blk, SMEM_P>>>(A2h, f2h, Acat2 + 256, 2048, 0.125f, 0, 512);
    // G3: Acat2[:,0:256) = fp16(lrelu(Acat1 @ W1^T))
    gemm_p<1><<<grid, blk, SMEM_P>>>(Acat1, Wh, Acat2, 512, 1.0f, 1, 512);
    // G4: out = lrelu(Acat2 @ W2^T)  fp32
    gemm_p<0><<<grid, blk, SMEM_P>>>(Acat2, Wh + 256 * 512, out, 512, 1.0f, 1, 256);
}

// round 13
// speedup vs baseline: 1.8107x; 1.0174x over previous
#include <cuda_runtime.h>
#include <cuda_fp16.h>
#include <cstdint>

// ============================================================================
// Gps, fp16 single-term mma.sync m16n8k16 (validated rel_err 4.400397e-4).
// R13: concurrency packing.
//   launch1: G1 (fused fp32-A GEMM, 256 CTAs) + fold4cvt (40 streaming CTAs)
//            in ONE 296-block launch -> fold's ~90us hides under G1.
//   launch2: G2 and G3 (independent pure-fp16 GEMMs) in one 512-block launch.
//   launch3: G4.
// All math bit-identical to R12.
// ============================================================================

#define ASTG 18432               // F: A stage 128 x 144B
#define OFFB 36864               // F: B stages at 36864 + s*18432
#define SMEM_F 73728
#define PSTG 36864               // P: stage = A 18432 + B 18432
#define SMEM_P (3 * 36864)       // 110592
#define LDW 36
#define NFOLD 40                 // fold team CTAs in launch1

__device__ __half g_A2h[16384 * 2048];
__device__ __half g_Acat1[16384 * 512];
__device__ __half g_Acat2[16384 * 512];
__device__ __half g_f1h[256 * 4096];
__device__ __half g_f2h[256 * 2048];
__device__ __half g_Wh[2][256 * 512];

__device__ __forceinline__ uint32_t smem_u32(const void* p) {
    uint32_t a;
    asm("{ .reg .u64 t; cvta.to.shared.u64 t, %1; cvt.u32.u64 %0, t; }" : "=r"(a) : "l"(p));
    return a;
}
__device__ __forceinline__ void cpa16(uint32_t dst, const void* src) {
    asm volatile("cp.async.cg.shared.global [%0], [%1], 16;" :: "r"(dst), "l"(src));
}
__device__ __forceinline__ uint32_t pk(__half a, __half b) {
    __half2 t; t.x = a; t.y = b;
    return *(uint32_t*)&t;
}
__device__ __forceinline__ void mma_f16(float* c, const uint32_t* a, const uint32_t* b) {
    asm volatile(
        "mma.sync.aligned.m16n8k16.row.col.f32.f16.f16.f32 "
        "{%0,%1,%2,%3}, {%4,%5,%6,%7}, {%8,%9}, {%0,%1,%2,%3};"
        : "+f"(c[0]), "+f"(c[1]), "+f"(c[2]), "+f"(c[3])
        : "r"(a[0]), "r"(a[1]), "r"(a[2]), "r"(a[3]), "r"(b[0]), "r"(b[1]));
}

// ---------------------------------------------------------------------------
// G1 body: C_half[16384, 256 @ ldc 512] = fp16(0.5 * A_fp32[16384,4096] @ B^T)
// fused fp32 LDG -> cvt -> STS A path, K-chunk 64, 2 stages.
// ---------------------------------------------------------------------------
__device__ __forceinline__ void gemm_f_body(
    const float* __restrict__ A, const __half* __restrict__ B,
    __half* __restrict__ C, int bidx, char* smem) {
    const uint32_t sb = smem_u32(smem);
    const int tid = threadIdx.x;
    const int l = tid & 31, wid = tid >> 5;
    const int wm = wid & 1, wn = wid >> 1;
    const int bn = bidx & 1, bm = bidx >> 1;
    const int NK = 64;

    float acc[4][4][4];
#pragma unroll
    for (int mt = 0; mt < 4; mt++)
#pragma unroll
        for (int nt = 0; nt < 4; nt++)
#pragma unroll
            for (int i = 0; i < 4; i++) acc[mt][nt][i] = 0.f;

    const int rbase = tid >> 4;
    const int kq = (tid & 15) << 2;

    auto ldgA = [&](int kc, int hb, float4* r) {
#pragma unroll
        for (int j = 0; j < 4; j++) {
            const int row = rbase + 16 * (hb * 4 + j);
            r[j] = *(const float4*)(A + (size_t)(bm * 128 + row) * 4096 +
                                    (kc << 6) + kq);
        }
    };
    auto stsA = [&](const float4* r, int hb, int s) {
        char* base = smem + s * ASTG;
        const int q = tid & 15;
#pragma unroll
        for (int j = 0; j < 4; j++) {
            const int row = rbase + 16 * (hb * 4 + j);
            uint2 h;
            h.x = pk(__float2half(r[j].x), __float2half(r[j].y));
            h.y = pk(__float2half(r[j].z), __float2half(r[j].w));
            *(uint2*)(base + row * 144 + q * 8) = h;
        }
    };
    auto fillB = [&](int kc, int s) {
#pragma unroll
        for (int j = 0; j < 4; j++) {
            const int g = tid + j * 256;
            const int row = g >> 3, q = g & 7;
            cpa16(sb + OFFB + s * ASTG + row * 144 + q * 16,
                  B + (size_t)(bn * 128 + row) * 4096 + (kc << 6) + q * 8);
        }
        asm volatile("cp.async.commit_group;" ::: "memory");
    };

    fillB(0, 0);
    {
        float4 a0[4];
        ldgA(0, 0, a0); stsA(a0, 0, 0);
        ldgA(0, 1, a0); stsA(a0, 1, 0);
    }

    for (int k = 0; k < NK; k++) {
        const int s = k & 1;
        asm volatile("cp.async.wait_group 0;" ::: "memory");
        __syncthreads();

        if (k + 1 < NK) fillB(k + 1, s ^ 1);
        float4 ar[4];
        if (k + 1 < NK) ldgA(k + 1, 0, ar);

        const uint32_t* Ah = (const uint32_t*)(smem + s * ASTG);
        const uint32_t* Bh = (const uint32_t*)(smem + OFFB + s * ASTG);
#pragma unroll
        for (int half = 0; half < 2; half++) {
#pragma unroll
            for (int ki = 0; ki < 2; ki++) {
                const int ks = half * 2 + ki;
                const int kw = ks * 8 + (l & 3);
                uint32_t a[4][4];
#pragma unroll
                for (int mt = 0; mt < 4; mt++) {
                    const int r = wm * 64 + mt * 16 + (l >> 2);
                    a[mt][0] = Ah[r * LDW + kw];
                    a[mt][1] = Ah[(r + 8) * LDW + kw];
                    a[mt][2] = Ah[r * LDW + kw + 4];
                    a[mt][3] = Ah[(r + 8) * LDW + kw + 4];
                }
#pragma unroll
                for (int nt = 0; nt < 4; nt++) {
                    const int n = wn * 32 + nt * 8 + (l >> 2);
                    uint32_t b[2];
                    b[0] = Bh[n * LDW + kw];
                    b[1] = Bh[n * LDW + kw + 4];
#pragma unroll
                    for (int mt = 0; mt < 4; mt++) mma_f16(acc[mt][nt], a[mt], b);
                }
            }
            if (k + 1 < NK) {
                stsA(ar, half, s ^ 1);
                if (half == 0) ldgA(k + 1, 1, ar);
            }
        }
    }

#pragma unroll
    for (int mt = 0; mt < 4; mt++) {
        const int r0 = bm * 128 + wm * 64 + mt * 16 + (l >> 2);
#pragma unroll
        for (int nt = 0; nt < 4; nt++) {
            const int c0 = bn * 128 + wn * 32 + nt * 8 + 2 * (l & 3);
#pragma unroll
            for (int h = 0; h < 2; h++) {
                const float vx = acc[mt][nt][2 * h + 0] * 0.5f;
                const float vy = acc[mt][nt][2 * h + 1] * 0.5f;
                *(uint32_t*)(C + (size_t)(r0 + h * 8) * 512 + c0) =
                    pk(__float2half(vx), __float2half(vy));
            }
        }
    }
}

// ---------------------------------------------------------------------------
// fold team body: A2h[m][k] = fp16(sum_{i<4} adj2[4m+i][k]).
// Grid-stride with 4-way ILP (16 independent LDG.128 in flight / thread).
// ---------------------------------------------------------------------------
__device__ __forceinline__ void fold_body(const float* __restrict__ in,
                                          __half* __restrict__ out, int team) {
    const int T = NFOLD * 256;
    const int idx = team * 256 + threadIdx.x;
    const int NJ = 16384 * 512;                      // uint2 output granules
    for (int j0 = idx; j0 < NJ; j0 += 4 * T) {
        float4 v[4][4];
        int jj[4];
#pragma unroll
        for (int u = 0; u < 4; u++) {
            jj[u] = j0 + u * T;
            if (jj[u] < NJ) {
                const int m = jj[u] >> 9, k4 = (jj[u] & 511) << 2;
                const float* p = in + (size_t)m * 4 * 2048 + k4;
                v[u][0] = *(const float4*)p;
                v[u][1] = *(const float4*)(p + 2048);
                v[u][2] = *(const float4*)(p + 4096);
                v[u][3] = *(const float4*)(p + 6144);
            }
        }
#pragma unroll
        for (int u = 0; u < 4; u++) {
            if (jj[u] < NJ) {
                const int m = jj[u] >> 9, k4 = (jj[u] & 511) << 2;
                uint2 h;
                h.x = pk(__float2half((v[u][0].x + v[u][1].x) + (v[u][2].x + v[u][3].x)),
                         __float2half((v[u][0].y + v[u][1].y) + (v[u][2].y + v[u][3].y)));
                h.y = pk(__float2half((v[u][0].z + v[u][1].z) + (v[u][2].z + v[u][3].z)),
                         __float2half((v[u][0].w + v[u][1].w) + (v[u][2].w + v[u][3].w)));
                *(uint2*)(out + (size_t)m * 2048 + k4) = h;
            }
        }
    }
}

// launch1: blocks [0,256) = G1, [256,296) = fold team
__global__ void __launch_bounds__(256, 2)
mega1(const float* __restrict__ adj1, const __half* __restrict__ f1h,
      __half* __restrict__ C, const float* __restrict__ adj2,
      __half* __restrict__ A2h) {
    extern __shared__ char smem[];
    if (blockIdx.x < 256) gemm_f_body(adj1, f1h, C, blockIdx.x, smem);
    else fold_body(adj2, A2h, blockIdx.x - 256);
}

// ---------------------------------------------------------------------------
// P body: pure-fp16 GEMM, both operands cp.async, 3 stages, K-chunk 64.
// ---------------------------------------------------------------------------
struct PD {
    const __half* A; const __half* B; void* C;
    int K; float scale; int lrelu; int ldc;
};

template <int EPIH>
__device__ __forceinline__ void gemm_p_body(const PD d, int bidx, char* smem) {
    const uint32_t sb = smem_u32(smem);
    const int tid = threadIdx.x;
    const int l = tid & 31, wid = tid >> 5;
    const int wm = wid & 1, wn = wid >> 1;
    const int bn = bidx & 1, bm = bidx >> 1;
    const int NK = d.K >> 6;

    float acc[4][4][4];
#pragma unroll
    for (int mt = 0; mt < 4; mt++)
#pragma unroll
        for (int nt = 0; nt < 4; nt++)
#pragma unroll
            for (int i = 0; i < 4; i++) acc[mt][nt][i] = 0.f;

    auto fill = [&](int kc, int st) {
        const uint32_t base = sb + st * PSTG;
        const int k0 = kc << 6;
#pragma unroll
        for (int j = 0; j < 4; j++) {
            const int g = tid + j * 256;
            const int row = g >> 3, q = g & 7;
            cpa16(base + row * 144 + q * 16,
                  d.A + (size_t)(bm * 128 + row) * d.K + k0 + q * 8);
            cpa16(base + 18432 + row * 144 + q * 16,
                  d.B + (size_t)(bn * 128 + row) * d.K + k0 + q * 8);
        }
    };

    fill(0, 0);
    asm volatile("cp.async.commit_group;" ::: "memory");
    fill(1, 1);
    asm volatile("cp.async.commit_group;" ::: "memory");

    int st = 0, stF = 2;
    for (int k = 0; k < NK; k++) {
        asm volatile("cp.async.wait_group 1;" ::: "memory");
        __syncthreads();

        if (k + 2 < NK) fill(k + 2, stF);
        asm volatile("cp.async.commit_group;" ::: "memory");

        const uint32_t* Ah = (const uint32_t*)(smem + st * PSTG);
        const uint32_t* Bh = (const uint32_t*)(smem + st * PSTG + 18432);
#pragma unroll
        for (int ks = 0; ks < 4; ks++) {
            const int kw = ks * 8 + (l & 3);
            uint32_t a[4][4];
#pragma unroll
            for (int mt = 0; mt < 4; mt++) {
                const int r = wm * 64 + mt * 16 + (l >> 2);
                a[mt][0] = Ah[r * LDW + kw];
                a[mt][1] = Ah[(r + 8) * LDW + kw];
                a[mt][2] = Ah[r * LDW + kw + 4];
                a[mt][3] = Ah[(r + 8) * LDW + kw + 4];
            }
#pragma unroll
            for (int nt = 0; nt < 4; nt++) {
                const int n = wn * 32 + nt * 8 + (l >> 2);
                uint32_t b[2];
                b[0] = Bh[n * LDW + kw];
                b[1] = Bh[n * LDW + kw + 4];
#pragma unroll
                for (int mt = 0; mt < 4; mt++) mma_f16(acc[mt][nt], a[mt], b);
            }
        }
        st++; if (st == 3) st = 0;
        stF++; if (stF == 3) stF = 0;
    }

#pragma unroll
    for (int mt = 0; mt < 4; mt++) {
        const int r0 = bm * 128 + wm * 64 + mt * 16 + (l >> 2);
#pragma unroll
        for (int nt = 0; nt < 4; nt++) {
            const int c0 = bn * 128 + wn * 32 + nt * 8 + 2 * (l & 3);
#pragma unroll
            for (int h = 0; h < 2; h++) {
                float vx = acc[mt][nt][2 * h + 0] * d.scale;
                float vy = acc[mt][nt][2 * h + 1] * d.scale;
                if (d.lrelu) {
                    vx = (vx >= 0.f) ? vx : 0.01f * vx;
                    vy = (vy >= 0.f) ? vy : 0.01f * vy;
                }
                if (EPIH) {
                    *(uint32_t*)((__half*)d.C + (size_t)(r0 + h * 8) * d.ldc + c0) =
                        pk(__float2half(vx), __float2half(vy));
                } else {
                    float2 v; v.x = vx; v.y = vy;
                    *(float2*)((float*)d.C + (size_t)(r0 + h * 8) * d.ldc + c0) = v;
                }
            }
        }
    }
}

// launch2: blocks [0,256) = G2, [256,512) = G3 (both half-epilogue)
__global__ void __launch_bounds__(256, 2)
mega2(PD d0, PD d1) {
    extern __shared__ char smem[];
    if (blockIdx.x < 256) gemm_p_body<1>(d0, blockIdx.x, smem);
    else gemm_p_body<1>(d1, blockIdx.x - 256, smem);
}
// launch3: G4 (float epilogue)
__global__ void __launch_bounds__(256, 2)
gemm_pf(PD d) {
    extern __shared__ char smem[];
    gemm_p_body<0>(d, blockIdx.x, smem);
}

// ---- prepasses ----
__global__ void gather_cvt(const float4* __restrict__ feat, const int* __restrict__ seed,
                           __half* __restrict__ acat) {
    const int g = blockIdx.x * 256 + threadIdx.x;
    const int m = g >> 6, q = g & 63;
    float4 v = feat[(size_t)seed[m] * 64 + q];
    uint2 h;
    h.x = pk(__float2half(v.x), __float2half(v.y));
    h.y = pk(__float2half(v.z), __float2half(v.w));
    *(uint2*)(acat + (size_t)m * 512 + q * 4) = h;
}
__global__ void tconv_h(const float* __restrict__ in, __half* __restrict__ o, int K) {
    __shared__ float t[32][33];
    const int k0 = blockIdx.x * 32, n0 = blockIdx.y * 32;
    const int tx = threadIdx.x, ty = threadIdx.y;
#pragma unroll
    for (int i = 0; i < 32; i += 8)
        t[ty + i][tx] = in[(size_t)(k0 + ty + i) * 256 + n0 + tx];
    __syncthreads();
#pragma unroll
    for (int i = 0; i < 32; i += 8)
        o[(size_t)(n0 + ty + i) * K + k0 + tx] = __float2half(t[tx][ty + i]);
}
__global__ void wconv2_h(const float* __restrict__ w1, const float* __restrict__ w2,
                         __half* __restrict__ o1, __half* __restrict__ o2) {
    const int i = blockIdx.x * 256 + threadIdx.x;
    if (i < 256 * 512) o1[i] = __float2half(w1[i]);
    else o2[i - 256 * 512] = __float2half(w2[i - 256 * 512]);
}

extern "C" void kernel_launch(void* const* d_in, const int* in_sizes, int n_in,
                              void* d_out, int out_size) {
    const float* feat = (const float*)d_in[0];
    const float* adj1 = (const float*)d_in[1];
    const float* f1 = (const float*)d_in[2];
    const float* adj2 = (const float*)d_in[3];
    const float* f2 = (const float*)d_in[4];
    const float* W1 = (const float*)d_in[5];
    const float* W2 = (const float*)d_in[6];
    const int* seed = (const int*)d_in[7];
    float* out = (float*)d_out;

    __half *A2h, *Acat1, *Acat2, *f1h, *f2h, *Wh;
    cudaGetSymbolAddress((void**)&A2h, g_A2h);
    cudaGetSymbolAddress((void**)&Acat1, g_Acat1);
    cudaGetSymbolAddress((void**)&Acat2, g_Acat2);
    cudaGetSymbolAddress((void**)&f1h, g_f1h);
    cudaGetSymbolAddress((void**)&f2h, g_f2h);
    cudaGetSymbolAddress((void**)&Wh, g_Wh);

    cudaFuncSetAttribute(mega1, cudaFuncAttributeMaxDynamicSharedMemorySize, SMEM_F);
    cudaFuncSetAttribute(mega2, cudaFuncAttributeMaxDynamicSharedMemorySize, SMEM_P);
    cudaFuncSetAttribute(gemm_pf, cudaFuncAttributeMaxDynamicSharedMemorySize, SMEM_P);

    // preps (small)
    tconv_h<<<dim3(128, 8), dim3(32, 8)>>>(f1, f1h, 4096);
    tconv_h<<<dim3(64, 8), dim3(32, 8)>>>(f2, f2h, 2048);
    wconv2_h<<<1024, 256>>>(W1, W2, Wh, Wh + 256 * 512);
    gather_cvt<<<4096, 256>>>((const float4*)feat, seed, Acat1);

    // launch1: G1 (Acat1[:,256:512) = fp16(0.5*adj1@f1)) + fold4cvt(adj2)
    mega1<<<256 + NFOLD, 256, SMEM_F>>>(adj1, f1h, Acat1 + 256, adj2, A2h);

    // launch2: G2 (Acat2[:,256:512)) and G3 (Acat2[:,0:256)) concurrently
    PD dG2 = {A2h, f2h, Acat2 + 256, 2048, 0.125f, 0, 512};
    PD dG3 = {Acat1, Wh, Acat2, 512, 1.0f, 1, 512};
    mega2<<<512, 256, SMEM_P>>>(dG2, dG3);

    // launch3: G4 -> out (fp32)
    PD dG4 = {Acat2, Wh + 256 * 512, out, 512, 1.0f, 1, 256};
    gemm_pf<<<256, 256, SMEM_P>>>(dG4);
}